// round 15
// baseline (speedup 1.0000x reference)
#include <cuda_runtime.h>
#include <cuda_fp16.h>
#include <cstdint>

// ---------------- scratch (no allocations allowed) ----------------
// gh: [bs=128][px=1024][c=128][2] fp16, (gate, hidden) interleaved per channel
__device__ __align__(16) __half g_ghh[33554432];
__device__ __align__(16) __half g_xh[8388608];      // [bs][px][ci=64] fp16
__device__ __align__(16) __half g_out0h[16777216];  // [bs][px][ci=128] fp16
__device__ __align__(16) __half g_B[442368];        // 27 chunks x [256 co'][64 k]
__device__ __align__(16) float g_bP[512];           // permuted bias, 2 layers
__device__ uint4 g_zero[8] = {};                    // 128 B zeros (halo cp source)

// ---------------- warp MMA helpers (baseline sm_80+ instructions) ----------
__device__ __forceinline__ uint32_t smem_u32(const void* p) {
    uint32_t a;
    asm("{ .reg .u64 t; cvta.to.shared.u64 t, %1; cvt.u32.u64 %0, t; }"
        : "=r"(a) : "l"(p));
    return a;
}
__device__ __forceinline__ void ldmx4(uint32_t* r, uint32_t a) {
    asm volatile("ldmatrix.sync.aligned.m8n8.x4.shared.b16 {%0,%1,%2,%3}, [%4];"
                 : "=r"(r[0]), "=r"(r[1]), "=r"(r[2]), "=r"(r[3]) : "r"(a));
}
__device__ __forceinline__ void mma16816(float* c, const uint32_t* a,
                                         uint32_t b0, uint32_t b1) {
    asm volatile(
        "mma.sync.aligned.m16n8k16.row.col.f32.f16.f16.f32 "
        "{%0,%1,%2,%3}, {%4,%5,%6,%7}, {%8,%9}, {%0,%1,%2,%3};"
        : "+f"(c[0]), "+f"(c[1]), "+f"(c[2]), "+f"(c[3])
        : "r"(a[0]), "r"(a[1]), "r"(a[2]), "r"(a[3]), "r"(b0), "r"(b1));
}
__device__ __forceinline__ void cp16(uint32_t d, const void* s) {
    asm volatile("cp.async.cg.shared.global [%0], [%1], 16;" :: "r"(d), "l"(s));
}
#define CP_COMMIT() asm volatile("cp.async.commit_group;" ::: "memory")
#define CP_WAIT0()  asm volatile("cp.async.wait_group 0;" ::: "memory")

// ---------------- weight prep: fp16 chunks, gate/hidden-interleaved rows ---
// Row permutation: original co (gate c: co=c; hidden c: co=128+c) maps to
// co' = 2c + t  (t=0 gate, t=1 hidden). D columns become co' -> gh layout
// [px][c][2]. Bias permuted identically into g_bP.
__global__ void prep_w_kernel(const float* __restrict__ w0,
                              const float* __restrict__ w1,
                              const float* __restrict__ b0,
                              const float* __restrict__ b1) {
    int e = blockIdx.x * 256 + threadIdx.x;   // grid = 1728 -> 442368 exact
    int g = e >> 14;
    int rem = e & 16383;
    int co = rem >> 6;
    int kk = rem & 63;
    const float* w;
    int CIN, tap, ci;
    if (g < 9) { w = w0; CIN = 64; tap = g; ci = kk; }
    else { int l = g - 9; w = w1; CIN = 128; tap = l % 9; ci = (l / 9) * 64 + kk; }
    int cop = (co < 128) ? (2 * co) : (2 * (co - 128) + 1);
    g_B[g * 16384 + cop * 64 + kk] = __float2half_rn(w[(co * CIN + ci) * 9 + tap]);
    if (blockIdx.x == 0) {
        int cop2 = threadIdx.x;               // 0..255
        int t = cop2 & 1, c = cop2 >> 1;
        g_bP[cop2] = b0[t * 128 + c];
        g_bP[256 + cop2] = b1[t * 128 + c];
    }
}

// ---------------- x prep: [bs][ci=64][px] fp32 -> [bs][px][ci] fp16 --------
__global__ void prep_x_kernel(const float* __restrict__ x) {
    __shared__ __half sm[128 * 72];   // [p 0..127][ci pad 72]
    const int bs = blockIdx.x, pxb = blockIdx.y;   // grid (128, 8)
    const int tid = threadIdx.x;
    const float* xb = x + (size_t)bs * 65536 + pxb * 128;
#pragma unroll
    for (int k = 0; k < 32; k++) {
        int i = tid + k * 256;        // 8192 = 64 ci * 128 px
        int ci = i >> 7, p = i & 127;
        sm[p * 72 + ci] = __float2half_rn(xb[ci * 1024 + p]);
    }
    __syncthreads();
    uint4* dst = (uint4*)(g_xh + (size_t)bs * 65536 + (size_t)pxb * 128 * 64);
#pragma unroll
    for (int k = 0; k < 4; k++) {
        int i = tid + k * 256;        // 1024 = 128 px * 8 segs
        int p = i >> 3, seg = i & 7;
        dst[p * 8 + seg] = *(uint4*)(sm + p * 72 + seg * 8);
    }
}

// ---------------- smem layout (bytes) ----------------
constexpr int RAW_SZ = 29376;       // 204 rows x 144 B ([y*34+x][ci 64 pad 72])
constexpr int B_SZ = 18432;

// ---------------- conv via warp-level fp16 MMA -----------------------------
// CTA = (4-row px tile, co' half, image bs). 256 threads / 8 warps.
// CTA tile: D[128 px][128 co']. Warp tile m32 x n64 (4m x 2n warps).
template <int CIN, bool XG>
__global__ void __launch_bounds__(256, 2)
conv_mma_kernel() {
    extern __shared__ char smem[];
    const uint32_t sb = smem_u32(smem);
    const int tid = threadIdx.x;
    const int wid = tid >> 5;
    const int lane = tid & 31;
    const int h0 = blockIdx.x * 4;     // 4 image rows
    const int coh = blockIdx.y;        // co' half 0..1
    const int bs = blockIdx.z;         // 0..127

    const uint32_t SMB0 = (CIN == 64) ? 29376u : 58752u;
    const uint32_t SMB1 = SMB0 + B_SZ;

    const __half* src = XG ? (g_out0h + (size_t)bs * 131072)
                           : (g_xh + (size_t)bs * 65536);
    const int SRC_STRIDE = XG ? 128 : 64;

    // warp tiling: 4 (m) x 2 (n)
    const int m0 = (wid & 3) * 32;
    const int n0r = (wid >> 2) * 64;
    // ldmatrix lane geometry (validated mapping)
    const int mrowA = (lane & 7) + ((lane >> 3) & 1) * 8;
    const int kcolA = (lane >> 4) * 8;
    const int noffB = (lane & 7) + (lane >> 4) * 8;
    const int koffB = ((lane >> 3) & 1) * 8;
    const int px0 = m0 + mrowA, px1 = px0 + 16;
    const uint32_t aB0 = sb +
        (uint32_t)(((px0 >> 5) * 34 + (px0 & 31)) * 144 + kcolA * 2);
    const uint32_t aB1 = sb +
        (uint32_t)(((px1 >> 5) * 34 + (px1 & 31)) * 144 + kcolA * 2);
    const uint32_t bLaneOff = (uint32_t)((n0r + noffB) * 144 + koffB * 2);

    float acc[2][8][4];
#pragma unroll
    for (int m = 0; m < 2; m++)
#pragma unroll
        for (int nb = 0; nb < 8; nb++)
#pragma unroll
            for (int j = 0; j < 4; j++) acc[m][nb][j] = 0.0f;

    const int g_first = (CIN == 64) ? 0 : 9;
    const int g_last  = g_first + 9 * (CIN / 64) - 1;

    auto stage_raw = [&](uint32_t dst, int hh) {
        const __half* s0 = src + hh * 64;
        for (int i = tid; i < 1632; i += 256) {      // 204 rows x 8 segs
            int row = i >> 3, seg = i & 7;
            int y = row / 34, xc = row - y * 34;
            int yy = h0 - 1 + y, xx = xc - 1;
            const void* sp = g_zero;
            if (yy >= 0 && yy < 32 && xx >= 0 && xx < 32)
                sp = s0 + (size_t)(yy * 32 + xx) * SRC_STRIDE + seg * 8;
            cp16(dst + row * 144 + seg * 16, sp);
        }
    };
    auto copy_B = [&](int g, uint32_t dst) {
        const uint4* sB = (const uint4*)(g_B + g * 16384 + coh * 8192);
#pragma unroll
        for (int i = tid; i < 1024; i += 256)
            cp16(dst + (i >> 3) * 144 + (i & 7) * 16, sB + i);
    };

    // ---- prologue: stage raw(cih0) + B(first tap), one group ----
    stage_raw(sb + 0, 0);
    copy_B(g_first, sb + SMB0);
    CP_COMMIT();
    int pb = 0;   // buffer holding the CURRENT tap's B

#pragma unroll 1
    for (int cih = 0; cih < CIN / 64; cih++) {
#pragma unroll 1
        for (int tap = 0; tap < 9; tap++) {
            const int g = g_first + cih * 9 + tap;

            CP_WAIT0();        // current B (and raw groups) complete
            __syncthreads();

            if (XG && g == g_first) {
                stage_raw(sb + RAW_SZ, 1);
                copy_B(g + 1, sb + (pb ? SMB0 : SMB1));
                CP_COMMIT();
            } else if (g < g_last) {
                copy_B(g + 1, sb + (pb ? SMB0 : SMB1));
                CP_COMMIT();
            }

            const uint32_t roff = (uint32_t)(cih * RAW_SZ) +
                (uint32_t)(((tap / 3) * 34 + (tap % 3)) * 144);
            const uint32_t a0 = aB0 + roff, a1 = aB1 + roff;
            const uint32_t bB = sb + (pb ? SMB1 : SMB0) + bLaneOff;

            // ---- 64 MMAs / warp ----
#pragma unroll
            for (int ks = 0; ks < 4; ks++) {
                const uint32_t kb = ks * 32;
                uint32_t Ah0[4], Ah1[4], Bf[4][4];
                ldmx4(Ah0, a0 + kb);
                ldmx4(Ah1, a1 + kb);
#pragma unroll
                for (int p = 0; p < 4; p++) ldmx4(Bf[p], bB + p * 2304 + kb);
#pragma unroll
                for (int p = 0; p < 4; p++) {
                    mma16816(acc[0][2 * p],     Ah0, Bf[p][0], Bf[p][1]);
                    mma16816(acc[1][2 * p],     Ah1, Bf[p][0], Bf[p][1]);
                    mma16816(acc[0][2 * p + 1], Ah0, Bf[p][2], Bf[p][3]);
                    mma16816(acc[1][2 * p + 1], Ah1, Bf[p][2], Bf[p][3]);
                }
            }
            pb ^= 1;
        }
    }

    // ---- epilogue: acc -> epi[px][co'] fp32 (pitch 132) -> gh fp16 ----
    __syncthreads();
    float* epi = (float*)smem;
#pragma unroll
    for (int m = 0; m < 2; m++) {
#pragma unroll
        for (int nb = 0; nb < 8; nb++) {
            int px = m0 + m * 16 + (lane >> 2);
            int co = n0r + nb * 8 + 2 * (lane & 3);
            *(float2*)(epi + px * 132 + co) =
                make_float2(acc[m][nb][0], acc[m][nb][1]);
            *(float2*)(epi + (px + 8) * 132 + co) =
                make_float2(acc[m][nb][2], acc[m][nb][3]);
        }
    }
    __syncthreads();
    {
        __half* ghb = g_ghh + ((size_t)bs * 1024 + h0 * 32) * 256 + coh * 128;
        const float4* bv4 = (const float4*)(g_bP + (XG ? 256 : 0) + coh * 128);
        for (int i = tid; i < 2048; i += 256) {
            int px = i >> 4, c8 = i & 15;
            float4 v0 = *(float4*)(epi + px * 132 + c8 * 8);
            float4 v1 = *(float4*)(epi + px * 132 + c8 * 8 + 4);
            float4 bb0 = __ldg(bv4 + c8 * 2);
            float4 bb1 = __ldg(bv4 + c8 * 2 + 1);
            __half2 h0p = __floats2half2_rn(v0.x + bb0.x, v0.y + bb0.y);
            __half2 h1p = __floats2half2_rn(v0.z + bb0.z, v0.w + bb0.w);
            __half2 h2p = __floats2half2_rn(v1.x + bb1.x, v1.y + bb1.y);
            __half2 h3p = __floats2half2_rn(v1.z + bb1.z, v1.w + bb1.w);
            uint4 o;
            o.x = *(uint32_t*)&h0p; o.y = *(uint32_t*)&h1p;
            o.z = *(uint32_t*)&h2p; o.w = *(uint32_t*)&h3p;
            *(uint4*)(ghb + (size_t)px * 256 + c8 * 8) = o;
        }
    }
}

// ---------------- scan 0: interleaved gh -> fp16 out0 + finals slot 0 ------
__global__ void scan0_kernel(float* __restrict__ dout) {
    const int tid = threadIdx.x;
    const int blk = blockIdx.x;           // 2048
    const int b = blk >> 9, pxb = blk & 511;
    const int px = pxb * 2 + (tid >> 7);
    const int c = tid & 127;

    // half2 view: (gate, hidden) for channel c at half2 index base + c
    const __half2* gb = (const __half2*)g_ghh +
                        ((size_t)(b * 32) * 1024 + px) * 128 + c;
    __half* ob = g_out0h + ((size_t)(b * 32) * 1024 + px) * 128 + c;

    float h = 0.5f;
#pragma unroll 8
    for (int s = 0; s < 32; s++) {
        float2 gf = __half22float2(*gb);
        gb += 131072;                     // 1024*128 half2 per s
        float z = 1.0f / (1.0f + __expf(-gf.x));
        float g = (gf.y >= 0.0f) ? (gf.y + 0.5f) : 1.0f / (1.0f + __expf(-gf.y));
        h += z * (g - h);
        *ob = __float2half_rn(h);
        ob += 131072;                     // 1024*128 half per s
    }
    dout[16777216 + (size_t)b * 131072 + c * 1024 + px] = h;
}

// ---------------- scan 1: interleaved gh -> c-major out + finals slot 1 ----
__global__ void scan1_kernel(float* __restrict__ dout) {
    __shared__ float tr[32][33];
    const int tid = threadIdx.x;
    const int blk = blockIdx.x;           // 512 = b(4) * cblk(4) * pxb(32)
    const int b = blk >> 7, rem = blk & 127;
    const int cblk = rem >> 5, pxb = rem & 31;
    const int c = cblk * 32 + (tid & 31);
    const int pg = tid >> 5;              // 0..7
    const int px0 = pxb * 32 + pg * 4;
    const int c2 = tid >> 3, pq = tid & 7;   // writer role

    float h[4] = {0.5f, 0.5f, 0.5f, 0.5f};
#pragma unroll 1
    for (int s = 0; s < 32; s++) {
        const __half2* gb = (const __half2*)g_ghh +
                            ((size_t)(b * 32 + s) * 1024 + px0) * 128 + c;
#pragma unroll
        for (int j = 0; j < 4; j++) {
            float2 gf = __half22float2(gb[j * 128]);
            float z = 1.0f / (1.0f + __expf(-gf.x));
            float g = (gf.y >= 0.0f) ? (gf.y + 0.5f)
                                     : 1.0f / (1.0f + __expf(-gf.y));
            h[j] += z * (g - h[j]);
        }
        __syncthreads();                  // previous iteration's readers done
#pragma unroll
        for (int j = 0; j < 4; j++) tr[pg * 4 + j][tid & 31] = h[j];
        __syncthreads();
        float4 v;
        v.x = tr[pq * 4 + 0][c2];
        v.y = tr[pq * 4 + 1][c2];
        v.z = tr[pq * 4 + 2][c2];
        v.w = tr[pq * 4 + 3][c2];
        *(float4*)(dout + ((size_t)((b * 32 + s) * 128) + cblk * 32 + c2) * 1024 +
                   pxb * 32 + pq * 4) = v;
    }
    float4 f = make_float4(h[0], h[1], h[2], h[3]);
    *(float4*)(dout + 16777216 + 524288 + (size_t)b * 131072 + c * 1024 + px0) = f;
}

// ---------------- launch ----------------
extern "C" void kernel_launch(void* const* d_in, const int* in_sizes, int n_in,
                              void* d_out, int out_size) {
    const float* x  = (const float*)d_in[0];
    const float* w0 = (const float*)d_in[1];
    const float* b0 = (const float*)d_in[2];
    const float* w1 = (const float*)d_in[3];
    const float* b1 = (const float*)d_in[4];
    float* out = (float*)d_out;

    constexpr int SMEM0 = 67584;    // conv0: raw + 2B; epi needs 67584
    constexpr int SMEM1 = 95616;    // conv1: 2 raw + 2B
    cudaFuncSetAttribute(conv_mma_kernel<64, false>,
                         cudaFuncAttributeMaxDynamicSharedMemorySize, SMEM0);
    cudaFuncSetAttribute(conv_mma_kernel<128, true>,
                         cudaFuncAttributeMaxDynamicSharedMemorySize, SMEM1);

    prep_w_kernel<<<1728, 256>>>(w0, w1, b0, b1);
    prep_x_kernel<<<dim3(128, 8), 256>>>(x);
    conv_mma_kernel<64, false><<<dim3(8, 2, 128), 256, SMEM0>>>();
    scan0_kernel<<<2048, 256>>>(out);
    conv_mma_kernel<128, true><<<dim3(8, 2, 128), 256, SMEM1>>>();
    scan1_kernel<<<512, 256>>>(out);
}

// round 16
// speedup vs baseline: 1.0466x; 1.0466x over previous
#include <cuda_runtime.h>
#include <cuda_fp16.h>
#include <cstdint>

// ---------------- scratch (no allocations allowed) ----------------
// gh: [bs=128][px=1024][c=128][2] fp16, (gate, hidden) interleaved per channel
__device__ __align__(16) __half g_ghh[33554432];
__device__ __align__(16) __half g_xh[8388608];      // [bs][px][ci=64] fp16
__device__ __align__(16) __half g_out0h[16777216];  // [bs][px][ci=128] fp16
// 27 chunks x [256 co'][64 k], XOR-swizzled within each 128B row
__device__ __align__(16) __half g_B[442368];
__device__ __align__(16) float g_bP[512];           // permuted bias, 2 layers
__device__ uint4 g_zero[8] = {};                    // 128 B zeros (halo cp source)

// ---------------- PTX helpers ----------------
__device__ __forceinline__ uint32_t smem_u32(const void* p) {
    uint32_t a;
    asm("{ .reg .u64 t; cvta.to.shared.u64 t, %1; cvt.u32.u64 %0, t; }"
        : "=r"(a) : "l"(p));
    return a;
}
__device__ __forceinline__ void ldmx4(uint32_t* r, uint32_t a) {
    asm volatile("ldmatrix.sync.aligned.m8n8.x4.shared.b16 {%0,%1,%2,%3}, [%4];"
                 : "=r"(r[0]), "=r"(r[1]), "=r"(r[2]), "=r"(r[3]) : "r"(a));
}
__device__ __forceinline__ void mma16816(float* c, const uint32_t* a,
                                         uint32_t b0, uint32_t b1) {
    asm volatile(
        "mma.sync.aligned.m16n8k16.row.col.f32.f16.f16.f32 "
        "{%0,%1,%2,%3}, {%4,%5,%6,%7}, {%8,%9}, {%0,%1,%2,%3};"
        : "+f"(c[0]), "+f"(c[1]), "+f"(c[2]), "+f"(c[3])
        : "r"(a[0]), "r"(a[1]), "r"(a[2]), "r"(a[3]), "r"(b0), "r"(b1));
}
__device__ __forceinline__ void cp16(uint32_t d, const void* s) {
    asm volatile("cp.async.cg.shared.global [%0], [%1], 16;" :: "r"(d), "l"(s));
}
#define CP_COMMIT() asm volatile("cp.async.commit_group;" ::: "memory")
#define CP_WAIT0()  asm volatile("cp.async.wait_group 0;" ::: "memory")

// Bulk copy (baseline sm_90): global -> shared::cta, mbarrier completion.
__device__ __forceinline__ void bulk_cp(uint32_t dst, const void* src,
                                        uint32_t bytes, uint32_t mbar) {
    asm volatile(
        "cp.async.bulk.shared::cta.global.mbarrier::complete_tx::bytes "
        "[%0], [%1], %2, [%3];"
        :: "r"(dst), "l"(src), "r"(bytes), "r"(mbar) : "memory");
}
#define MBARRIER_INIT(mb, c) \
    asm volatile("mbarrier.init.shared.b64 [%0], %1;" \
                 :: "r"((uint32_t)(mb)), "r"((uint32_t)(c)) : "memory")
#define MBARRIER_EXPECT_TX(mb, bytes) \
    asm volatile("mbarrier.arrive.expect_tx.shared.b64 _, [%0], %1;" \
                 :: "r"((uint32_t)(mb)), "r"((uint32_t)(bytes)) : "memory")
#define MBARRIER_WAIT_PARITY(mb, ph) do { \
    uint32_t _mb = (uint32_t)(mb), _p = (uint32_t)(ph), _d; \
    asm volatile("{ .reg .pred p; mbarrier.try_wait.parity.acquire.cta.shared::cta.b64 p, [%1], %2; selp.b32 %0,1,0,p; }" \
                 : "=r"(_d) : "r"(_mb), "r"(_p) : "memory"); \
    if (!_d) { \
        asm volatile("{ .reg .pred P1;\nWL_%=:\n mbarrier.try_wait.parity.acquire.cta.shared::cta.b64 P1, [%0], %1, 0x989680;\n @P1 bra.uni WD_%=;\n bra.uni WL_%=;\nWD_%=:\n}" \
                     :: "r"(_mb), "r"(_p) : "memory"); \
    } } while (0)

// ---------------- weight prep: swizzled fp16 chunks, interleaved rows ------
// co' = 2c + t (t=0 gate, t=1 hidden). Within each 128B row (64 halfs),
// 16B segment seg is stored at seg' = seg ^ (co' & 7)  (XOR-8 swizzle so a
// verbatim bulk copy yields conflict-free ldmatrix).
__global__ void prep_w_kernel(const float* __restrict__ w0,
                              const float* __restrict__ w1,
                              const float* __restrict__ b0,
                              const float* __restrict__ b1) {
    int e = blockIdx.x * 256 + threadIdx.x;   // grid = 1728 -> 442368 exact
    int g = e >> 14;
    int rem = e & 16383;
    int co = rem >> 6;
    int kk = rem & 63;
    const float* w;
    int CIN, tap, ci;
    if (g < 9) { w = w0; CIN = 64; tap = g; ci = kk; }
    else { int l = g - 9; w = w1; CIN = 128; tap = l % 9; ci = (l / 9) * 64 + kk; }
    int cop = (co < 128) ? (2 * co) : (2 * (co - 128) + 1);
    int seg = (kk >> 3) ^ (cop & 7);
    g_B[g * 16384 + cop * 64 + seg * 8 + (kk & 7)] =
        __float2half_rn(w[(co * CIN + ci) * 9 + tap]);
    if (blockIdx.x == 0) {
        int cop2 = threadIdx.x;               // 0..255
        int t = cop2 & 1, c = cop2 >> 1;
        g_bP[cop2] = b0[t * 128 + c];
        g_bP[256 + cop2] = b1[t * 128 + c];
    }
}

// ---------------- x prep: [bs][ci=64][px] fp32 -> [bs][px][ci] fp16 --------
__global__ void prep_x_kernel(const float* __restrict__ x) {
    __shared__ __half sm[128 * 72];   // [p 0..127][ci pad 72]
    const int bs = blockIdx.x, pxb = blockIdx.y;   // grid (128, 8)
    const int tid = threadIdx.x;
    const float* xb = x + (size_t)bs * 65536 + pxb * 128;
#pragma unroll
    for (int k = 0; k < 32; k++) {
        int i = tid + k * 256;        // 8192 = 64 ci * 128 px
        int ci = i >> 7, p = i & 127;
        sm[p * 72 + ci] = __float2half_rn(xb[ci * 1024 + p]);
    }
    __syncthreads();
    uint4* dst = (uint4*)(g_xh + (size_t)bs * 65536 + (size_t)pxb * 128 * 64);
#pragma unroll
    for (int k = 0; k < 4; k++) {
        int i = tid + k * 256;        // 1024 = 128 px * 8 segs
        int p = i >> 3, seg = i & 7;
        dst[p * 8 + seg] = *(uint4*)(sm + p * 72 + seg * 8);
    }
}

// ---------------- smem layout (bytes) ----------------
constexpr int RAW_SZ = 29376;       // 204 rows x 144 B ([y*34+x][ci 64 pad 72])
constexpr int B_SZ = 16384;         // 128 rows x 128 B, pre-swizzled

// ---------------- conv via warp-level fp16 MMA -----------------------------
// CTA = (4-row px tile, co' half, image bs). 256 threads / 8 warps.
// CTA tile: D[128 px][128 co']. Warp tile m32 x n64 (4m x 2n warps).
// B arrives by single-instruction bulk copies (double-buffered, mbarrier
// completion); A staging stays cp.async into padded rows.
template <int CIN, bool XG>
__global__ void __launch_bounds__(256, 2)
conv_mma_kernel() {
    extern __shared__ char smem[];
    const uint32_t sb = smem_u32(smem);
    const int tid = threadIdx.x;
    const int wid = tid >> 5;
    const int lane = tid & 31;
    const int h0 = blockIdx.x * 4;     // 4 image rows
    const int coh = blockIdx.y;        // co' half 0..1
    const int bs = blockIdx.z;         // 0..127

    const uint32_t SMB0 = (CIN == 64) ? 29376u : 58752u;
    const uint32_t SMB1 = SMB0 + B_SZ;
    const uint32_t SMMB = SMB1 + B_SZ;           // 2 mbarriers (16 B)

    const __half* src = XG ? (g_out0h + (size_t)bs * 131072)
                           : (g_xh + (size_t)bs * 65536);
    const int SRC_STRIDE = XG ? 128 : 64;

    // warp tiling: 4 (m) x 2 (n)
    const int m0 = (wid & 3) * 32;
    const int n0r = (wid >> 2) * 64;
    // ldmatrix lane geometry (validated mapping)
    const int mrowA = (lane & 7) + ((lane >> 3) & 1) * 8;
    const int kcolA = (lane >> 4) * 8;
    const int noffB = (lane & 7) + (lane >> 4) * 8;
    const int koffB2 = ((lane >> 3) & 1) * 16;      // bytes
    const uint32_t xorv = (uint32_t)((lane & 7) << 4);
    const int px0 = m0 + mrowA, px1 = px0 + 16;
    const uint32_t aB0 = sb +
        (uint32_t)(((px0 >> 5) * 34 + (px0 & 31)) * 144 + kcolA * 2);
    const uint32_t aB1 = sb +
        (uint32_t)(((px1 >> 5) * 34 + (px1 & 31)) * 144 + kcolA * 2);
    const uint32_t bRow = (uint32_t)((n0r + noffB) * 128);

    float acc[2][8][4];
#pragma unroll
    for (int m = 0; m < 2; m++)
#pragma unroll
        for (int nb = 0; nb < 8; nb++)
#pragma unroll
            for (int j = 0; j < 4; j++) acc[m][nb][j] = 0.0f;

    const int g_first = (CIN == 64) ? 0 : 9;
    const int g_last  = g_first + 9 * (CIN / 64) - 1;

    auto stage_raw = [&](uint32_t dst, int hh) {
        const __half* s0 = src + hh * 64;
        for (int i = tid; i < 1632; i += 256) {      // 204 rows x 8 segs
            int row = i >> 3, seg = i & 7;
            int y = row / 34, xc = row - y * 34;
            int yy = h0 - 1 + y, xx = xc - 1;
            const void* sp = g_zero;
            if (yy >= 0 && yy < 32 && xx >= 0 && xx < 32)
                sp = s0 + (size_t)(yy * 32 + xx) * SRC_STRIDE + seg * 8;
            cp16(dst + row * 144 + seg * 16, sp);
        }
    };
    auto issue_B = [&](int g, uint32_t dst, uint32_t mbar) {
        MBARRIER_EXPECT_TX(mbar, B_SZ);
        bulk_cp(dst, (const char*)g_B + (size_t)g * 32768 + coh * 16384,
                B_SZ, mbar);
    };

    // ---- prologue: raw(cih0) via cp.async; B(first) via bulk ----
    stage_raw(sb + 0, 0);
    CP_COMMIT();
    if (tid == 0) {
        MBARRIER_INIT(SMMB, 1);
        MBARRIER_INIT(SMMB + 8, 1);
    }
    __syncthreads();           // mbarriers visible before first expect_tx
    if (tid == 0) issue_B(g_first, sb + SMB0, SMMB);

    int pb = 0;
    int phase[2] = {0, 0};

#pragma unroll 1
    for (int cih = 0; cih < CIN / 64; cih++) {
#pragma unroll 1
        for (int tap = 0; tap < 9; tap++) {
            const int g = g_first + cih * 9 + tap;

            if (tap == 0) CP_WAIT0();       // this cih's raw cp.asyncs done
            MBARRIER_WAIT_PARITY(SMMB + pb * 8, phase[pb]);
            phase[pb] ^= 1;
            __syncthreads();   // raw published; prev tap's B reads finished

            if (tid == 0 && g < g_last)
                issue_B(g + 1, sb + (pb ? SMB0 : SMB1), SMMB + (1 - pb) * 8);
            if (XG && g == g_first) {       // prefetch raw(cih1) under MMAs
                stage_raw(sb + RAW_SZ, 1);
                CP_COMMIT();
            }

            const uint32_t roff = (uint32_t)(cih * RAW_SZ) +
                (uint32_t)(((tap / 3) * 34 + (tap % 3)) * 144);
            const uint32_t a0 = aB0 + roff, a1 = aB1 + roff;
            const uint32_t bB = sb + (pb ? SMB1 : SMB0) + bRow;

            // ---- 64 MMAs / warp ----
#pragma unroll
            for (int ks = 0; ks < 4; ks++) {
                const uint32_t colx = (uint32_t)(koffB2 + ks * 32) ^ xorv;
                uint32_t Ah0[4], Ah1[4], Bf[4][4];
                ldmx4(Ah0, a0 + ks * 32);
                ldmx4(Ah1, a1 + ks * 32);
#pragma unroll
                for (int p = 0; p < 4; p++) ldmx4(Bf[p], bB + p * 2048 + colx);
#pragma unroll
                for (int p = 0; p < 4; p++) {
                    mma16816(acc[0][2 * p],     Ah0, Bf[p][0], Bf[p][1]);
                    mma16816(acc[1][2 * p],     Ah1, Bf[p][0], Bf[p][1]);
                    mma16816(acc[0][2 * p + 1], Ah0, Bf[p][2], Bf[p][3]);
                    mma16816(acc[1][2 * p + 1], Ah1, Bf[p][2], Bf[p][3]);
                }
            }
            pb ^= 1;
        }
    }

    // ---- epilogue: acc -> epi[px][co'] fp32 (pitch 132) -> gh fp16 ----
    __syncthreads();           // all MMAs done; no bulk in flight (last tap)
    float* epi = (float*)smem;
#pragma unroll
    for (int m = 0; m < 2; m++) {
#pragma unroll
        for (int nb = 0; nb < 8; nb++) {
            int px = m0 + m * 16 + (lane >> 2);
            int co = n0r + nb * 8 + 2 * (lane & 3);
            *(float2*)(epi + px * 132 + co) =
                make_float2(acc[m][nb][0], acc[m][nb][1]);
            *(float2*)(epi + (px + 8) * 132 + co) =
                make_float2(acc[m][nb][2], acc[m][nb][3]);
        }
    }
    __syncthreads();
    {
        __half* ghb = g_ghh + ((size_t)bs * 1024 + h0 * 32) * 256 + coh * 128;
        const float4* bv4 = (const float4*)(g_bP + (XG ? 256 : 0) + coh * 128);
        for (int i = tid; i < 2048; i += 256) {
            int px = i >> 4, c8 = i & 15;
            float4 v0 = *(float4*)(epi + px * 132 + c8 * 8);
            float4 v1 = *(float4*)(epi + px * 132 + c8 * 8 + 4);
            float4 bb0 = __ldg(bv4 + c8 * 2);
            float4 bb1 = __ldg(bv4 + c8 * 2 + 1);
            __half2 h0p = __floats2half2_rn(v0.x + bb0.x, v0.y + bb0.y);
            __half2 h1p = __floats2half2_rn(v0.z + bb0.z, v0.w + bb0.w);
            __half2 h2p = __floats2half2_rn(v1.x + bb1.x, v1.y + bb1.y);
            __half2 h3p = __floats2half2_rn(v1.z + bb1.z, v1.w + bb1.w);
            uint4 o;
            o.x = *(uint32_t*)&h0p; o.y = *(uint32_t*)&h1p;
            o.z = *(uint32_t*)&h2p; o.w = *(uint32_t*)&h3p;
            *(uint4*)(ghb + (size_t)px * 256 + c8 * 8) = o;
        }
    }
}

// ---------------- scan 0: interleaved gh -> fp16 out0 + finals slot 0 ------
__global__ void scan0_kernel(float* __restrict__ dout) {
    const int tid = threadIdx.x;
    const int blk = blockIdx.x;           // 2048
    const int b = blk >> 9, pxb = blk & 511;
    const int px = pxb * 2 + (tid >> 7);
    const int c = tid & 127;

    const __half2* gb = (const __half2*)g_ghh +
                        ((size_t)(b * 32) * 1024 + px) * 128 + c;
    __half* ob = g_out0h + ((size_t)(b * 32) * 1024 + px) * 128 + c;

    float h = 0.5f;
#pragma unroll 8
    for (int s = 0; s < 32; s++) {
        float2 gf = __half22float2(*gb);
        gb += 131072;                     // 1024*128 half2 per s
        float z = 1.0f / (1.0f + __expf(-gf.x));
        float g = (gf.y >= 0.0f) ? (gf.y + 0.5f) : 1.0f / (1.0f + __expf(-gf.y));
        h += z * (g - h);
        *ob = __float2half_rn(h);
        ob += 131072;                     // 1024*128 half per s
    }
    dout[16777216 + (size_t)b * 131072 + c * 1024 + px] = h;
}

// ---------------- scan 1: interleaved gh -> c-major out + finals slot 1 ----
__global__ void scan1_kernel(float* __restrict__ dout) {
    __shared__ float tr[32][33];
    const int tid = threadIdx.x;
    const int blk = blockIdx.x;           // 512 = b(4) * cblk(4) * pxb(32)
    const int b = blk >> 7, rem = blk & 127;
    const int cblk = rem >> 5, pxb = rem & 31;
    const int c = cblk * 32 + (tid & 31);
    const int pg = tid >> 5;              // 0..7
    const int px0 = pxb * 32 + pg * 4;
    const int c2 = tid >> 3, pq = tid & 7;   // writer role

    float h[4] = {0.5f, 0.5f, 0.5f, 0.5f};
#pragma unroll 1
    for (int s = 0; s < 32; s++) {
        const __half2* gb = (const __half2*)g_ghh +
                            ((size_t)(b * 32 + s) * 1024 + px0) * 128 + c;
#pragma unroll
        for (int j = 0; j < 4; j++) {
            float2 gf = __half22float2(gb[j * 128]);
            float z = 1.0f / (1.0f + __expf(-gf.x));
            float g = (gf.y >= 0.0f) ? (gf.y + 0.5f)
                                     : 1.0f / (1.0f + __expf(-gf.y));
            h[j] += z * (g - h[j]);
        }
        __syncthreads();                  // previous iteration's readers done
#pragma unroll
        for (int j = 0; j < 4; j++) tr[pg * 4 + j][tid & 31] = h[j];
        __syncthreads();
        float4 v;
        v.x = tr[pq * 4 + 0][c2];
        v.y = tr[pq * 4 + 1][c2];
        v.z = tr[pq * 4 + 2][c2];
        v.w = tr[pq * 4 + 3][c2];
        *(float4*)(dout + ((size_t)((b * 32 + s) * 128) + cblk * 32 + c2) * 1024 +
                   pxb * 32 + pq * 4) = v;
    }
    float4 f = make_float4(h[0], h[1], h[2], h[3]);
    *(float4*)(dout + 16777216 + 524288 + (size_t)b * 131072 + c * 1024 + px0) = f;
}

// ---------------- launch ----------------
extern "C" void kernel_launch(void* const* d_in, const int* in_sizes, int n_in,
                              void* d_out, int out_size) {
    const float* x  = (const float*)d_in[0];
    const float* w0 = (const float*)d_in[1];
    const float* b0 = (const float*)d_in[2];
    const float* w1 = (const float*)d_in[3];
    const float* b1 = (const float*)d_in[4];
    float* out = (float*)d_out;

    // conv0: raw(29376) + 2B(32768) + mbars(16) = 62160; epi needs 67584
    // conv1: 2 raw(58752) + 2B(32768) + mbars(16) = 91536
    constexpr int SMEM0 = 67584;
    constexpr int SMEM1 = 91536;
    cudaFuncSetAttribute(conv_mma_kernel<64, false>,
                         cudaFuncAttributeMaxDynamicSharedMemorySize, SMEM0);
    cudaFuncSetAttribute(conv_mma_kernel<128, true>,
                         cudaFuncAttributeMaxDynamicSharedMemorySize, SMEM1);

    prep_w_kernel<<<1728, 256>>>(w0, w1, b0, b1);
    prep_x_kernel<<<dim3(128, 8), 256>>>(x);
    conv_mma_kernel<64, false><<<dim3(8, 2, 128), 256, SMEM0>>>();
    scan0_kernel<<<2048, 256>>>(out);
    conv_mma_kernel<128, true><<<dim3(8, 2, 128), 256, SMEM1>>>();
    scan1_kernel<<<512, 256>>>(out);
}

// round 17
// speedup vs baseline: 1.2590x; 1.2029x over previous
#include <cuda_runtime.h>
#include <cuda_fp16.h>
#include <cstdint>

// ---------------- scratch (no allocations allowed) ----------------
// gh: [bs=128][px=1024][c=128][2] fp16, (gate, hidden) interleaved per channel
__device__ __align__(16) __half g_ghh[33554432];
__device__ __align__(16) __half g_xh[8388608];      // [bs][px][ci=64] fp16
__device__ __align__(16) __half g_out0h[16777216];  // [bs][px][ci=128] fp16
// 27 chunks x [256 co'][64 k], XOR-swizzled within each 128B row
__device__ __align__(16) __half g_B[442368];
__device__ __align__(16) float g_bP[512];           // permuted bias, 2 layers
__device__ uint4 g_zero[8] = {};                    // 128 B zeros (halo cp source)

// ---------------- PTX helpers ----------------
__device__ __forceinline__ uint32_t smem_u32(const void* p) {
    uint32_t a;
    asm("{ .reg .u64 t; cvta.to.shared.u64 t, %1; cvt.u32.u64 %0, t; }"
        : "=r"(a) : "l"(p));
    return a;
}
__device__ __forceinline__ void ldmx4(uint32_t* r, uint32_t a) {
    asm volatile("ldmatrix.sync.aligned.m8n8.x4.shared.b16 {%0,%1,%2,%3}, [%4];"
                 : "=r"(r[0]), "=r"(r[1]), "=r"(r[2]), "=r"(r[3]) : "r"(a));
}
__device__ __forceinline__ void mma16816(float* c, const uint32_t* a,
                                         uint32_t b0, uint32_t b1) {
    asm volatile(
        "mma.sync.aligned.m16n8k16.row.col.f32.f16.f16.f32 "
        "{%0,%1,%2,%3}, {%4,%5,%6,%7}, {%8,%9}, {%0,%1,%2,%3};"
        : "+f"(c[0]), "+f"(c[1]), "+f"(c[2]), "+f"(c[3])
        : "r"(a[0]), "r"(a[1]), "r"(a[2]), "r"(a[3]), "r"(b0), "r"(b1));
}
__device__ __forceinline__ void cp16(uint32_t d, const void* s) {
    asm volatile("cp.async.cg.shared.global [%0], [%1], 16;" :: "r"(d), "l"(s));
}
#define CP_COMMIT() asm volatile("cp.async.commit_group;" ::: "memory")
#define CP_WAIT0()  asm volatile("cp.async.wait_group 0;" ::: "memory")

// Bulk copy (baseline sm_90): global -> shared::cta, mbarrier completion.
__device__ __forceinline__ void bulk_cp(uint32_t dst, const void* src,
                                        uint32_t bytes, uint32_t mbar) {
    asm volatile(
        "cp.async.bulk.shared::cta.global.mbarrier::complete_tx::bytes "
        "[%0], [%1], %2, [%3];"
        :: "r"(dst), "l"(src), "r"(bytes), "r"(mbar) : "memory");
}
#define MBARRIER_INIT(mb, c) \
    asm volatile("mbarrier.init.shared.b64 [%0], %1;" \
                 :: "r"((uint32_t)(mb)), "r"((uint32_t)(c)) : "memory")
#define MBARRIER_EXPECT_TX(mb, bytes) \
    asm volatile("mbarrier.arrive.expect_tx.shared.b64 _, [%0], %1;" \
                 :: "r"((uint32_t)(mb)), "r"((uint32_t)(bytes)) : "memory")
#define MBARRIER_WAIT_PARITY(mb, ph) do { \
    uint32_t _mb = (uint32_t)(mb), _p = (uint32_t)(ph), _d; \
    asm volatile("{ .reg .pred p; mbarrier.try_wait.parity.acquire.cta.shared::cta.b64 p, [%1], %2; selp.b32 %0,1,0,p; }" \
                 : "=r"(_d) : "r"(_mb), "r"(_p) : "memory"); \
    if (!_d) { \
        asm volatile("{ .reg .pred P1;\nWL_%=:\n mbarrier.try_wait.parity.acquire.cta.shared::cta.b64 P1, [%0], %1, 0x989680;\n @P1 bra.uni WD_%=;\n bra.uni WL_%=;\nWD_%=:\n}" \
                     :: "r"(_mb), "r"(_p) : "memory"); \
    } } while (0)

// ---------------- weight prep: swizzled fp16 chunks, interleaved rows ------
// co' = 2c + t (t=0 gate, t=1 hidden). Within each 128B row (64 halfs),
// 16B segment seg is stored at seg' = seg ^ (co' & 7).
__global__ void prep_w_kernel(const float* __restrict__ w0,
                              const float* __restrict__ w1,
                              const float* __restrict__ b0,
                              const float* __restrict__ b1) {
    int e = blockIdx.x * 256 + threadIdx.x;   // grid = 1728 -> 442368 exact
    int g = e >> 14;
    int rem = e & 16383;
    int co = rem >> 6;
    int kk = rem & 63;
    const float* w;
    int CIN, tap, ci;
    if (g < 9) { w = w0; CIN = 64; tap = g; ci = kk; }
    else { int l = g - 9; w = w1; CIN = 128; tap = l % 9; ci = (l / 9) * 64 + kk; }
    int cop = (co < 128) ? (2 * co) : (2 * (co - 128) + 1);
    int seg = (kk >> 3) ^ (cop & 7);
    g_B[g * 16384 + cop * 64 + seg * 8 + (kk & 7)] =
        __float2half_rn(w[(co * CIN + ci) * 9 + tap]);
    if (blockIdx.x == 0) {
        int cop2 = threadIdx.x;               // 0..255
        int t = cop2 & 1, c = cop2 >> 1;
        g_bP[cop2] = b0[t * 128 + c];
        g_bP[256 + cop2] = b1[t * 128 + c];
    }
}

// ---------------- x prep: [bs][ci=64][px] fp32 -> [bs][px][ci] fp16 --------
__global__ void prep_x_kernel(const float* __restrict__ x) {
    __shared__ __half sm[128 * 72];   // [p 0..127][ci pad 72]
    const int bs = blockIdx.x, pxb = blockIdx.y;   // grid (128, 8)
    const int tid = threadIdx.x;
    const float* xb = x + (size_t)bs * 65536 + pxb * 128;
#pragma unroll
    for (int k = 0; k < 32; k++) {
        int i = tid + k * 256;        // 8192 = 64 ci * 128 px
        int ci = i >> 7, p = i & 127;
        sm[p * 72 + ci] = __float2half_rn(xb[ci * 1024 + p]);
    }
    __syncthreads();
    uint4* dst = (uint4*)(g_xh + (size_t)bs * 65536 + (size_t)pxb * 128 * 64);
#pragma unroll
    for (int k = 0; k < 4; k++) {
        int i = tid + k * 256;        // 1024 = 128 px * 8 segs
        int p = i >> 3, seg = i & 7;
        dst[p * 8 + seg] = *(uint4*)(sm + p * 72 + seg * 8);
    }
}

// ---------------- smem layout (bytes) ----------------
constexpr int RAW_SZ = 29376;       // 204 rows x 144 B ([y*34+x][ci 64 pad 72])
constexpr int B_SZ = 16384;         // 128 rows x 128 B, pre-swizzled

// ---------------- conv via warp-level fp16 MMA (unchanged from R16) --------
template <int CIN, bool XG>
__global__ void __launch_bounds__(256, 2)
conv_mma_kernel() {
    extern __shared__ char smem[];
    const uint32_t sb = smem_u32(smem);
    const int tid = threadIdx.x;
    const int wid = tid >> 5;
    const int lane = tid & 31;
    const int h0 = blockIdx.x * 4;     // 4 image rows
    const int coh = blockIdx.y;        // co' half 0..1
    const int bs = blockIdx.z;         // 0..127

    const uint32_t SMB0 = (CIN == 64) ? 29376u : 58752u;
    const uint32_t SMB1 = SMB0 + B_SZ;
    const uint32_t SMMB = SMB1 + B_SZ;           // 2 mbarriers (16 B)

    const __half* src = XG ? (g_out0h + (size_t)bs * 131072)
                           : (g_xh + (size_t)bs * 65536);
    const int SRC_STRIDE = XG ? 128 : 64;

    const int m0 = (wid & 3) * 32;
    const int n0r = (wid >> 2) * 64;
    const int mrowA = (lane & 7) + ((lane >> 3) & 1) * 8;
    const int kcolA = (lane >> 4) * 8;
    const int noffB = (lane & 7) + (lane >> 4) * 8;
    const int koffB2 = ((lane >> 3) & 1) * 16;      // bytes
    const uint32_t xorv = (uint32_t)((lane & 7) << 4);
    const int px0 = m0 + mrowA, px1 = px0 + 16;
    const uint32_t aB0 = sb +
        (uint32_t)(((px0 >> 5) * 34 + (px0 & 31)) * 144 + kcolA * 2);
    const uint32_t aB1 = sb +
        (uint32_t)(((px1 >> 5) * 34 + (px1 & 31)) * 144 + kcolA * 2);
    const uint32_t bRow = (uint32_t)((n0r + noffB) * 128);

    float acc[2][8][4];
#pragma unroll
    for (int m = 0; m < 2; m++)
#pragma unroll
        for (int nb = 0; nb < 8; nb++)
#pragma unroll
            for (int j = 0; j < 4; j++) acc[m][nb][j] = 0.0f;

    const int g_first = (CIN == 64) ? 0 : 9;
    const int g_last  = g_first + 9 * (CIN / 64) - 1;

    auto stage_raw = [&](uint32_t dst, int hh) {
        const __half* s0 = src + hh * 64;
        for (int i = tid; i < 1632; i += 256) {      // 204 rows x 8 segs
            int row = i >> 3, seg = i & 7;
            int y = row / 34, xc = row - y * 34;
            int yy = h0 - 1 + y, xx = xc - 1;
            const void* sp = g_zero;
            if (yy >= 0 && yy < 32 && xx >= 0 && xx < 32)
                sp = s0 + (size_t)(yy * 32 + xx) * SRC_STRIDE + seg * 8;
            cp16(dst + row * 144 + seg * 16, sp);
        }
    };
    auto issue_B = [&](int g, uint32_t dst, uint32_t mbar) {
        MBARRIER_EXPECT_TX(mbar, B_SZ);
        bulk_cp(dst, (const char*)g_B + (size_t)g * 32768 + coh * 16384,
                B_SZ, mbar);
    };

    stage_raw(sb + 0, 0);
    CP_COMMIT();
    if (tid == 0) {
        MBARRIER_INIT(SMMB, 1);
        MBARRIER_INIT(SMMB + 8, 1);
    }
    __syncthreads();
    if (tid == 0) issue_B(g_first, sb + SMB0, SMMB);

    int pb = 0;
    int phase[2] = {0, 0};

#pragma unroll 1
    for (int cih = 0; cih < CIN / 64; cih++) {
#pragma unroll 1
        for (int tap = 0; tap < 9; tap++) {
            const int g = g_first + cih * 9 + tap;

            if (tap == 0) CP_WAIT0();
            MBARRIER_WAIT_PARITY(SMMB + pb * 8, phase[pb]);
            phase[pb] ^= 1;
            __syncthreads();

            if (tid == 0 && g < g_last)
                issue_B(g + 1, sb + (pb ? SMB0 : SMB1), SMMB + (1 - pb) * 8);
            if (XG && g == g_first) {
                stage_raw(sb + RAW_SZ, 1);
                CP_COMMIT();
            }

            const uint32_t roff = (uint32_t)(cih * RAW_SZ) +
                (uint32_t)(((tap / 3) * 34 + (tap % 3)) * 144);
            const uint32_t a0 = aB0 + roff, a1 = aB1 + roff;
            const uint32_t bB = sb + (pb ? SMB1 : SMB0) + bRow;

#pragma unroll
            for (int ks = 0; ks < 4; ks++) {
                const uint32_t colx = (uint32_t)(koffB2 + ks * 32) ^ xorv;
                uint32_t Ah0[4], Ah1[4], Bf[4][4];
                ldmx4(Ah0, a0 + ks * 32);
                ldmx4(Ah1, a1 + ks * 32);
#pragma unroll
                for (int p = 0; p < 4; p++) ldmx4(Bf[p], bB + p * 2048 + colx);
#pragma unroll
                for (int p = 0; p < 4; p++) {
                    mma16816(acc[0][2 * p],     Ah0, Bf[p][0], Bf[p][1]);
                    mma16816(acc[1][2 * p],     Ah1, Bf[p][0], Bf[p][1]);
                    mma16816(acc[0][2 * p + 1], Ah0, Bf[p][2], Bf[p][3]);
                    mma16816(acc[1][2 * p + 1], Ah1, Bf[p][2], Bf[p][3]);
                }
            }
            pb ^= 1;
        }
    }

    __syncthreads();
    float* epi = (float*)smem;
#pragma unroll
    for (int m = 0; m < 2; m++) {
#pragma unroll
        for (int nb = 0; nb < 8; nb++) {
            int px = m0 + m * 16 + (lane >> 2);
            int co = n0r + nb * 8 + 2 * (lane & 3);
            *(float2*)(epi + px * 132 + co) =
                make_float2(acc[m][nb][0], acc[m][nb][1]);
            *(float2*)(epi + (px + 8) * 132 + co) =
                make_float2(acc[m][nb][2], acc[m][nb][3]);
        }
    }
    __syncthreads();
    {
        __half* ghb = g_ghh + ((size_t)bs * 1024 + h0 * 32) * 256 + coh * 128;
        const float4* bv4 = (const float4*)(g_bP + (XG ? 256 : 0) + coh * 128);
        for (int i = tid; i < 2048; i += 256) {
            int px = i >> 4, c8 = i & 15;
            float4 v0 = *(float4*)(epi + px * 132 + c8 * 8);
            float4 v1 = *(float4*)(epi + px * 132 + c8 * 8 + 4);
            float4 bb0 = __ldg(bv4 + c8 * 2);
            float4 bb1 = __ldg(bv4 + c8 * 2 + 1);
            __half2 h0p = __floats2half2_rn(v0.x + bb0.x, v0.y + bb0.y);
            __half2 h1p = __floats2half2_rn(v0.z + bb0.z, v0.w + bb0.w);
            __half2 h2p = __floats2half2_rn(v1.x + bb1.x, v1.y + bb1.y);
            __half2 h3p = __floats2half2_rn(v1.z + bb1.z, v1.w + bb1.w);
            uint4 o;
            o.x = *(uint32_t*)&h0p; o.y = *(uint32_t*)&h1p;
            o.z = *(uint32_t*)&h2p; o.w = *(uint32_t*)&h3p;
            *(uint4*)(ghb + (size_t)px * 256 + c8 * 8) = o;
        }
    }
}

// ---------------- scan 0: batched-MLP loads, 2 x 16 steps ------------------
__device__ __forceinline__ float scan_step(uint32_t gv, float h) {
    __half2 hv = *(__half2*)&gv;
    float2 gf = __half22float2(hv);
    float z = 1.0f / (1.0f + __expf(-gf.x));
    float g = (gf.y >= 0.0f) ? (gf.y + 0.5f) : 1.0f / (1.0f + __expf(-gf.y));
    return h + z * (g - h);
}

__global__ void scan0_kernel(float* __restrict__ dout) {
    const int tid = threadIdx.x;
    const int blk = blockIdx.x;           // 2048
    const int b = blk >> 9, pxb = blk & 511;
    const int px = pxb * 2 + (tid >> 7);
    const int c = tid & 127;

    const uint32_t* gb = (const uint32_t*)g_ghh +
                         ((size_t)(b * 32) * 1024 + px) * 128 + c;
    __half* ob = g_out0h + ((size_t)(b * 32) * 1024 + px) * 128 + c;

    float h = 0.5f;
#pragma unroll
    for (int half = 0; half < 2; half++) {
        uint32_t gv[16];
#pragma unroll
        for (int s = 0; s < 16; s++)
            gv[s] = gb[(size_t)(half * 16 + s) * 131072];
#pragma unroll
        for (int s = 0; s < 16; s++) {
            h = scan_step(gv[s], h);
            ob[(size_t)(half * 16 + s) * 131072] = __float2half_rn(h);
        }
    }
    dout[16777216 + (size_t)b * 131072 + c * 1024 + px] = h;
}

// ---------------- scan 1: prefetch + double-buffered transpose -------------
__global__ void scan1_kernel(float* __restrict__ dout) {
    __shared__ float tr[2][32][33];
    const int tid = threadIdx.x;
    const int blk = blockIdx.x;           // 512 = b(4) * cblk(4) * pxb(32)
    const int b = blk >> 7, rem = blk & 127;
    const int cblk = rem >> 5, pxb = rem & 31;
    const int c = cblk * 32 + (tid & 31);
    const int pg = tid >> 5;              // 0..7
    const int px0 = pxb * 32 + pg * 4;
    const int c2 = tid >> 3, pq = tid & 7;   // writer role

    const uint32_t* gbase = (const uint32_t*)g_ghh +
                            ((size_t)(b * 32) * 1024 + px0) * 128 + c;

    float h[4] = {0.5f, 0.5f, 0.5f, 0.5f};
    uint32_t cur[4];
#pragma unroll
    for (int j = 0; j < 4; j++) cur[j] = gbase[j * 128];

#pragma unroll 1
    for (int s = 0; s < 32; s++) {
        uint32_t nxt[4];
        if (s < 31) {
            const uint32_t* gn = gbase + (size_t)(s + 1) * 131072;
#pragma unroll
            for (int j = 0; j < 4; j++) nxt[j] = gn[j * 128];
        }
#pragma unroll
        for (int j = 0; j < 4; j++) h[j] = scan_step(cur[j], h[j]);
        const int sl = s & 1;
#pragma unroll
        for (int j = 0; j < 4; j++) tr[sl][pg * 4 + j][tid & 31] = h[j];
        __syncthreads();
        float4 v;
        v.x = tr[sl][pq * 4 + 0][c2];
        v.y = tr[sl][pq * 4 + 1][c2];
        v.z = tr[sl][pq * 4 + 2][c2];
        v.w = tr[sl][pq * 4 + 3][c2];
        *(float4*)(dout + ((size_t)((b * 32 + s) * 128) + cblk * 32 + c2) * 1024 +
                   pxb * 32 + pq * 4) = v;
#pragma unroll
        for (int j = 0; j < 4; j++) cur[j] = nxt[j];
    }
    float4 f = make_float4(h[0], h[1], h[2], h[3]);
    *(float4*)(dout + 16777216 + 524288 + (size_t)b * 131072 + c * 1024 + px0) = f;
}

// ---------------- launch ----------------
extern "C" void kernel_launch(void* const* d_in, const int* in_sizes, int n_in,
                              void* d_out, int out_size) {
    const float* x  = (const float*)d_in[0];
    const float* w0 = (const float*)d_in[1];
    const float* b0 = (const float*)d_in[2];
    const float* w1 = (const float*)d_in[3];
    const float* b1 = (const float*)d_in[4];
    float* out = (float*)d_out;

    constexpr int SMEM0 = 67584;    // conv0: raw + 2B + mbars; epi needs 67584
    constexpr int SMEM1 = 91536;    // conv1: 2 raw + 2B + mbars
    cudaFuncSetAttribute(conv_mma_kernel<64, false>,
                         cudaFuncAttributeMaxDynamicSharedMemorySize, SMEM0);
    cudaFuncSetAttribute(conv_mma_kernel<128, true>,
                         cudaFuncAttributeMaxDynamicSharedMemorySize, SMEM1);

    prep_w_kernel<<<1728, 256>>>(w0, w1, b0, b1);
    prep_x_kernel<<<dim3(128, 8), 256>>>(x);
    conv_mma_kernel<64, false><<<dim3(8, 2, 128), 256, SMEM0>>>();
    scan0_kernel<<<2048, 256>>>(out);
    conv_mma_kernel<128, true><<<dim3(8, 2, 128), 256, SMEM1>>>();
    scan1_kernel<<<512, 256>>>(out);
}